// round 12
// baseline (speedup 1.0000x reference)
#include <cuda_runtime.h>
#include <cuda_bf16.h>

// Problem constants
#define BB 4
#define CC 3
#define HW 45056            // 256*176 = 88*512
#define SS 5
#define MM 18
#define SMN (SS*MM)         // 90
#define TILE 512            // hw scalars per block tile
#define NTILES (HW/TILE)    // 88
#define NGROUP 5
#define TPB (SMN/NGROUP)    // 18 tasks per block
#define NWARP 3
#define THREADS (NWARP*32)  // 96
#define TPWARP (TPB/NWARP)  // 6 tasks per warp -> 3 groups of T=2
#define CHUNK 256           // floats per cp.async chunk (1KB, one task, half tile)
#define NPAIR 6             // chunk-pairs per warp: 3 groups * 2
#define NCOMP 16
#define TOTAL_BLOCKS (NTILES*BB*NGROUP)   // 1760

#define SMEM_TILE_F (6*TILE)              // 3072 floats (12KB)
#define SMEM_RING_F (NWARP*4*CHUNK)       // 3072 floats (12KB)
#define SMEM_TOTAL_B ((SMEM_TILE_F + SMEM_RING_F)*4)   // 24576 B

#define K1C 0.0001f
#define K2C 0.0009f
#define EPSF 1e-6f

// zero at module load; finalizing block re-zeroes after use so every
// kernel_launch / graph replay starts from zeros.
__device__ float g_part[BB * SMN * NCOMP];
__device__ unsigned int g_count;

// ---------- f32x2 packed math helpers (sm_103a) ----------
typedef unsigned long long ull;
__device__ __forceinline__ void upk2(ull v, float& lo, float& hi) {
    asm("mov.b64 {%0, %1}, %2;" : "=f"(lo), "=f"(hi) : "l"(v));
}
__device__ __forceinline__ ull mul2(ull a, ull b) {
    ull r; asm("mul.rn.f32x2 %0, %1, %2;" : "=l"(r) : "l"(a), "l"(b)); return r;
}
__device__ __forceinline__ ull add2(ull a, ull b) {
    ull r; asm("add.rn.f32x2 %0, %1, %2;" : "=l"(r) : "l"(a), "l"(b)); return r;
}
__device__ __forceinline__ ull fma2(ull a, ull b, ull c) {
    ull r; asm("fma.rn.f32x2 %0, %1, %2, %3;" : "=l"(r) : "l"(a), "l"(b), "l"(c)); return r;
}
__device__ __forceinline__ ull lds64(const float* p) {
    return *(const ull*)p;    // 8B-aligned shared load -> LDS.64
}

// ---------- cp.async helpers ----------
__device__ __forceinline__ void cp_chunk_nc(float* dst, const float* src, int lane) {
    #pragma unroll
    for (int j = 0; j < 2; j++) {
        unsigned d = (unsigned)__cvta_generic_to_shared(dst + (j * 32 + lane) * 4);
        asm volatile("cp.async.cg.shared.global [%0], [%1], 16;\n"
                     :: "r"(d), "l"(src + (j * 32 + lane) * 4));
    }
}
__device__ __forceinline__ void cp_commit() {
    asm volatile("cp.async.commit_group;\n" ::: "memory");
}
template <int N> __device__ __forceinline__ void cp_wait() {
    asm volatile("cp.async.wait_group %0;\n" :: "n"(N) : "memory");
}

// accumulate one mask f32x2 pair into one task's 16 accumulators
__device__ __forceinline__ void accum(ull* a, ull m,
                                      ull x0, ull x1, ull x2,
                                      ull y0, ull y1, ull y2) {
    a[0] = add2(a[0], m);
    ull t, u;
    t = mul2(m, x0); u = mul2(m, y0);
    a[1] = add2(a[1], t);  a[2] = add2(a[2], u);
    a[3] = fma2(t, x0, a[3]); a[4] = fma2(u, y0, a[4]); a[5] = fma2(t, y0, a[5]);
    t = mul2(m, x1); u = mul2(m, y1);
    a[6] = add2(a[6], t);  a[7] = add2(a[7], u);
    a[8] = fma2(t, x1, a[8]); a[9] = fma2(u, y1, a[9]); a[10] = fma2(t, y1, a[10]);
    t = mul2(m, x2); u = mul2(m, y2);
    a[11] = add2(a[11], t); a[12] = add2(a[12], u);
    a[13] = fma2(t, x2, a[13]); a[14] = fma2(u, y2, a[14]); a[15] = fma2(t, y2, a[15]);
}
// map accumulate slot -> g_part component order {S, mx,my,mxx,myy,mxy per ch}
// a[0]=S; ch c: a[1+5c..5+5c] = {mx,my,mxx,myy,mxy}  -> matches epilogue layout below

// ---------- single fused kernel ----------
// grid (NTILES, BB, NGROUP) = 1760 blocks, 96 threads, target 6 blocks/SM
__global__ void __launch_bounds__(THREADS, 6)
fused_kernel(const float* __restrict__ X,
             const float* __restrict__ Y,
             const float* __restrict__ Mk,
             float* __restrict__ out) {
    extern __shared__ __align__(16) float smem[];
    float* tile = smem;                    // [6][TILE]
    float* ring = smem + SMEM_TILE_F;      // [NWARP][4][CHUNK]
    __shared__ unsigned int s_last;

    const int b    = blockIdx.y;
    const int t0   = blockIdx.x * TILE;
    const int gz   = blockIdx.z;
    const int tid  = threadIdx.x;
    const int warp = tid >> 5;
    const int lane = tid & 31;

    const int task0 = gz * TPB + warp * TPWARP;     // warp's first task
    const float* mbase = Mk + ((size_t)(b * SMN + task0)) * (size_t)HW + t0;
    float* ringw = ring + warp * (4 * CHUNK);

    // issue a chunk-pair p: tasks 2*(p/2), 2*(p/2)+1, tile-half p%2, slots (2p)&3,(2p)&3+1
    auto issue_pair = [&](int p) {
        const int lt0  = (p >> 1) * 2;
        const int c    = p & 1;
        const int slot = (2 * p) & 3;
        cp_chunk_nc(ringw + slot * CHUNK,
                    mbase + (size_t)lt0 * HW + c * CHUNK, lane);
        cp_chunk_nc(ringw + (slot + 1) * CHUNK,
                    mbase + (size_t)(lt0 + 1) * HW + c * CHUNK, lane);
        cp_commit();
    };

    // --- prologue: 2 chunk-pairs in flight before anything else ---
    issue_pair(0);
    issue_pair(1);

    // --- fill tile with rescaled X', Y' (768 float4 over 96 threads) ---
    const float4* X4 = (const float4*)X;
    const float4* Y4 = (const float4*)Y;
    #pragma unroll
    for (int r = 0; r < 8; r++) {
        int idx = r * THREADS + tid;       // 0..767
        int ch  = idx >> 7;                // /128
        int pos = idx & 127;
        float4 v = (ch < 3) ? X4[((b * 3 + ch) * HW + t0) / 4 + pos]
                            : Y4[((b * 3 + (ch - 3)) * HW + t0) / 4 + pos];
        v.x = fmaf(v.x, 0.5f, 0.5f);
        v.y = fmaf(v.y, 0.5f, 0.5f);
        v.z = fmaf(v.z, 0.5f, 0.5f);
        v.w = fmaf(v.w, 0.5f, 0.5f);
        *(float4*)&tile[ch * TILE + pos * 4] = v;
    }
    __syncthreads();

    // 2 tasks x 16 f32x2 accumulators
    ull acc0[16], acc1[16];
    #pragma unroll
    for (int k = 0; k < 16; k++) { acc0[k] = 0ULL; acc1[k] = 0ULL; }

    #pragma unroll 1
    for (int p = 0; p < NPAIR; p++) {
        if (p == NPAIR - 1) cp_wait<0>(); else cp_wait<1>();

        const int c    = p & 1;
        const int slot = (2 * p) & 3;
        const float* m0c = ringw + slot * CHUNK;
        const float* m1c = ringw + (slot + 1) * CHUNK;

        #pragma unroll
        for (int u = 0; u < 4; u++) {
            const int moff = u * 64 + 2 * lane;
            const int base = c * CHUNK + moff;
            // register-resident features for this position pair
            ull x0 = lds64(&tile[0 * TILE + base]);
            ull x1 = lds64(&tile[1 * TILE + base]);
            ull x2 = lds64(&tile[2 * TILE + base]);
            ull y0 = lds64(&tile[3 * TILE + base]);
            ull y1 = lds64(&tile[4 * TILE + base]);
            ull y2 = lds64(&tile[5 * TILE + base]);
            ull m0 = lds64(&m0c[moff]);
            ull m1 = lds64(&m1c[moff]);
            accum(acc0, m0, x0, x1, x2, y0, y1, y2);
            accum(acc1, m1, x0, x1, x2, y0, y1, y2);
        }

        if (p + 2 < NPAIR) issue_pair(p + 2);

        // group end: reduce both tasks across warp, lane 0 commits
        if (c == 1) {
            float v[32];
            #pragma unroll
            for (int k = 0; k < 16; k++) {
                float lo, hi;
                upk2(acc0[k], lo, hi); v[k] = lo + hi;
                upk2(acc1[k], lo, hi); v[16 + k] = lo + hi;
                acc0[k] = 0ULL; acc1[k] = 0ULL;
            }
            #pragma unroll
            for (int off = 16; off > 0; off >>= 1) {
                #pragma unroll
                for (int k = 0; k < 32; k++)
                    v[k] += __shfl_xor_sync(0xffffffffu, v[k], off);
            }
            if (lane == 0) {
                float* pp = &g_part[((size_t)b * SMN + task0 + (p >> 1) * 2) * NCOMP];
                #pragma unroll
                for (int k = 0; k < 32; k++) atomicAdd(pp + k, v[k]);
            }
        }
    }

    // ---------------- last-block finalize (R8-validated pattern) ----------------
    __syncthreads();   // all warps in this block have issued their g_part atomics
    if (tid == 0) {
        __threadfence();                               // make our atomics visible
        unsigned int r = atomicAdd(&g_count, 1u);
        s_last = (r == TOTAL_BLOCKS - 1) ? 1u : 0u;
    }
    __syncthreads();
    if (!s_last) return;

    __threadfence();   // acquire-side ordering before reading g_part

    // reuse smem for the tiny epilogue accumulators
    float* csb = tile;          // [BB*SS] = 20
    float* ssb = tile + 32;
    if (tid < BB * SS) { csb[tid] = 0.0f; ssb[tid] = 0.0f; }
    __syncthreads();

    for (int idx = tid; idx < BB * SMN * CC; idx += THREADS) {
        int bb = idx / (SMN * CC);
        int r2 = idx % (SMN * CC);
        int s  = r2 / (MM * CC);
        int mc = r2 % (MM * CC);
        int m  = mc / CC;
        int c  = mc % CC;
        const float* p = &g_part[((size_t)bb * SMN + s * MM + m) * NCOMP];
        float inv  = __fdividef(1.0f, p[0] + EPSF);
        float mu1  = p[1 + c * 5 + 0] * inv;
        float mu2  = p[1 + c * 5 + 1] * inv;
        float mu11 = p[1 + c * 5 + 2] * inv;
        float mu22 = p[1 + c * 5 + 3] * inv;
        float mu12 = p[1 + c * 5 + 4] * inv;
        float s1  = mu11 - mu1 * mu1;
        float s2  = mu22 - mu2 * mu2;
        float s12 = mu12 - mu1 * mu2;
        float cs   = __fdividef(2.0f * s12 + K2C, s1 + s2 + K2C);
        float ssim = __fdividef(2.0f * mu1 * mu2 + K1C, mu1 * mu1 + mu2 * mu2 + K1C) * cs;
        cs   = fmaxf(cs, 0.0f);
        ssim = fmaxf(ssim, 0.0f);
        atomicAdd(&csb[bb * SS + s], cs);
        atomicAdd(&ssb[bb * SS + s], ssim);
    }
    __syncthreads();

    // re-zero partials + counter for the next invocation / graph replay
    for (int i = tid; i < BB * SMN * NCOMP; i += THREADS) g_part[i] = 0.0f;
    if (tid == 1) g_count = 0u;

    if (tid == 0) {
        const float invMC = 1.0f / (float)(MM * CC);
        float accb = 0.0f;
        #pragma unroll
        for (int bb = 0; bb < BB; bb++) {
            float prod = ssb[bb * SS + (SS - 1)] * invMC;
            #pragma unroll
            for (int s = 0; s < SS - 1; s++) prod *= csb[bb * SS + s] * invMC;
            accb += prod;
        }
        out[0] = accb / (float)BB;
    }
}

extern "C" void kernel_launch(void* const* d_in, const int* in_sizes, int n_in,
                              void* d_out, int out_size) {
    const float* X  = (const float*)d_in[0];
    const float* Y  = (const float*)d_in[1];
    const float* Mk = (const float*)d_in[2];
    float* out = (float*)d_out;

    cudaFuncSetAttribute(fused_kernel,
                         cudaFuncAttributeMaxDynamicSharedMemorySize, SMEM_TOTAL_B);
    dim3 grid(NTILES, BB, NGROUP);
    fused_kernel<<<grid, THREADS, SMEM_TOTAL_B>>>(X, Y, Mk, out);
}

// round 13
// speedup vs baseline: 1.5802x; 1.5802x over previous
#include <cuda_runtime.h>
#include <cuda_bf16.h>

// Problem constants
#define BB 4
#define CC 3
#define HW 45056            // 256*176 = 44*1024
#define SS 5
#define MM 18
#define SMN (SS*MM)         // 90
#define TILE 1024           // hw scalars per block tile
#define NTILES (HW/TILE)    // 44
#define NGROUP 3
#define TPB (SMN/NGROUP)    // 30 tasks per block
#define NPAIRB (TPB/2)      // 15 task-pairs per block
#define NWARP 8
#define THREADS (NWARP*32)  // 256
#define CHUNK 256           // floats per task per pipeline chunk (1KB)
#define SLOT (2*CHUNK)      // ring slot: 2KB = chunk for both tasks of a pair
#define NSLOT 4             // ring depth: 4 slots -> 3 chunks in flight
#define RINGW (NSLOT*SLOT)  // 2048 floats per warp
#define NCOMP 16
#define TOTAL_BLOCKS (NTILES*BB*NGROUP)   // 528

#define SMEM_TILE_F (6*TILE)              // 6144 floats (24KB)
#define SMEM_RING_F (NWARP*RINGW)         // 16384 floats (64KB)
#define SMEM_TOTAL_B ((SMEM_TILE_F + SMEM_RING_F)*4)   // 90112 B

#define K1C 0.0001f
#define K2C 0.0009f
#define EPSF 1e-6f

// zero at module load; finalizing block re-zeroes after use so every
// kernel_launch / graph replay starts from zeros.
__device__ float g_part[BB * SMN * NCOMP];
__device__ unsigned int g_count;

// ---------- f32x2 packed math helpers (sm_103a) ----------
typedef unsigned long long ull;
__device__ __forceinline__ void upk2(ull v, float& lo, float& hi) {
    asm("mov.b64 {%0, %1}, %2;" : "=f"(lo), "=f"(hi) : "l"(v));
}
__device__ __forceinline__ ull mul2(ull a, ull b) {
    ull r; asm("mul.rn.f32x2 %0, %1, %2;" : "=l"(r) : "l"(a), "l"(b)); return r;
}
__device__ __forceinline__ ull add2(ull a, ull b) {
    ull r; asm("add.rn.f32x2 %0, %1, %2;" : "=l"(r) : "l"(a), "l"(b)); return r;
}
__device__ __forceinline__ ull fma2(ull a, ull b, ull c) {
    ull r; asm("fma.rn.f32x2 %0, %1, %2, %3;" : "=l"(r) : "l"(a), "l"(b), "l"(c)); return r;
}
__device__ __forceinline__ ull lds64(const float* p) {
    return *(const ull*)p;    // 8B-aligned shared load -> LDS.64
}

// ---------- cp.async helpers ----------
__device__ __forceinline__ void cp_chunk_nc(float* dst, const float* src, int lane) {
    #pragma unroll
    for (int j = 0; j < 2; j++) {
        unsigned d = (unsigned)__cvta_generic_to_shared(dst + (j * 32 + lane) * 4);
        asm volatile("cp.async.cg.shared.global [%0], [%1], 16;\n"
                     :: "r"(d), "l"(src + (j * 32 + lane) * 4));
    }
}
__device__ __forceinline__ void cp_commit() {
    asm volatile("cp.async.commit_group;\n" ::: "memory");
}
template <int N> __device__ __forceinline__ void cp_wait() {
    asm volatile("cp.async.wait_group %0;\n" :: "n"(N) : "memory");
}

// accumulate one mask f32x2 into one task's 16 accumulators (features shared)
__device__ __forceinline__ void accum(ull* a, ull m,
                                      ull x0, ull x1, ull x2,
                                      ull y0, ull y1, ull y2) {
    a[0] = add2(a[0], m);
    ull t, u;
    t = mul2(m, x0); u = mul2(m, y0);
    a[1] = add2(a[1], t);  a[2] = add2(a[2], u);
    a[3] = fma2(t, x0, a[3]); a[4] = fma2(u, y0, a[4]); a[5] = fma2(t, y0, a[5]);
    t = mul2(m, x1); u = mul2(m, y1);
    a[6] = add2(a[6], t);  a[7] = add2(a[7], u);
    a[8] = fma2(t, x1, a[8]); a[9] = fma2(u, y1, a[9]); a[10] = fma2(t, y1, a[10]);
    t = mul2(m, x2); u = mul2(m, y2);
    a[11] = add2(a[11], t); a[12] = add2(a[12], u);
    a[13] = fma2(t, x2, a[13]); a[14] = fma2(u, y2, a[14]); a[15] = fma2(t, y2, a[15]);
}
// a[0]=S; ch c: a[1+5c..5+5c] = {mx,my,mxx,myy,mxy}  (matches epilogue layout)

// ---------- single fused kernel ----------
// grid (NTILES, BB, NGROUP) = 528 blocks, 256 threads, 2 blocks/SM
__global__ void __launch_bounds__(THREADS, 2)
fused_kernel(const float* __restrict__ X,
             const float* __restrict__ Y,
             const float* __restrict__ Mk,
             float* __restrict__ out) {
    extern __shared__ __align__(16) float smem[];
    float* tile = smem;                    // [6][TILE]
    float* ring = smem + SMEM_TILE_F;      // [NWARP][NSLOT][SLOT]
    __shared__ unsigned int s_last;

    const int b    = blockIdx.y;
    const int t0   = blockIdx.x * TILE;
    const int gz   = blockIdx.z;
    const int tid  = threadIdx.x;
    const int warp = tid >> 5;
    const int lane = tid & 31;

    float* ringw = ring + warp * RINGW;

    // warp handles pairs pr = warp, warp+8 (warp 7: only pr=7). 15 pairs total.
    const int npw    = (warp < NPAIRB - NWARP) ? 2 : 1;   // warps 0..6 -> 2, warp 7 -> 1
    const int totseq = npw * 4;                            // pair-chunks for this warp

    // issue pair-chunk s: pair pr = warp + 8*(s>>2), tile-chunk c = s&3, slot s&3
    auto issue_seq = [&](int s) {
        const int pr = warp + NWARP * (s >> 2);
        const int c  = s & 3;
        const float* src = Mk + ((size_t)(b * SMN + gz * TPB + 2 * pr)) * (size_t)HW
                              + t0 + c * CHUNK;
        float* dst = ringw + (s & 3) * SLOT;
        cp_chunk_nc(dst,         src,      lane);   // even task, 1KB
        cp_chunk_nc(dst + CHUNK, src + HW, lane);   // odd task, 1KB
        cp_commit();
    };

    // --- prologue: 3 pair-chunks (6KB) in flight before anything else ---
    issue_seq(0);
    issue_seq(1);
    issue_seq(2);

    // --- fill tile with rescaled X', Y' (1536 float4 over 256 threads) ---
    const float4* X4 = (const float4*)X;
    const float4* Y4 = (const float4*)Y;
    #pragma unroll
    for (int r = 0; r < 6; r++) {
        int idx = r * THREADS + tid;       // 0..1535
        int ch  = idx >> 8;                // /256
        int pos = idx & 255;
        float4 v = (ch < 3) ? X4[((b * 3 + ch) * HW + t0) / 4 + pos]
                            : Y4[((b * 3 + (ch - 3)) * HW + t0) / 4 + pos];
        v.x = fmaf(v.x, 0.5f, 0.5f);
        v.y = fmaf(v.y, 0.5f, 0.5f);
        v.z = fmaf(v.z, 0.5f, 0.5f);
        v.w = fmaf(v.w, 0.5f, 0.5f);
        *(float4*)&tile[ch * TILE + pos * 4] = v;
    }
    __syncthreads();

    // 2 tasks x 16 f32x2 accumulators
    ull acc0[16], acc1[16];
    #pragma unroll
    for (int k = 0; k < 16; k++) { acc0[k] = 0ULL; acc1[k] = 0ULL; }

    #pragma unroll 1
    for (int i = 0; i < totseq; i++) {
        // chunk i must be complete: pending groups = min(totseq-i, 3)
        const int rem = totseq - i;
        if (rem >= 3) cp_wait<2>();
        else if (rem == 2) cp_wait<1>();
        else cp_wait<0>();

        const float* mr = ringw + (i & 3) * SLOT;
        const int cbase = (i & 3) * CHUNK;

        #pragma unroll
        for (int u = 0; u < 4; u++) {
            const int moff = u * 64 + 2 * lane;
            const int base = cbase + moff;
            ull x0 = lds64(&tile[0 * TILE + base]);
            ull x1 = lds64(&tile[1 * TILE + base]);
            ull x2 = lds64(&tile[2 * TILE + base]);
            ull y0 = lds64(&tile[3 * TILE + base]);
            ull y1 = lds64(&tile[4 * TILE + base]);
            ull y2 = lds64(&tile[5 * TILE + base]);
            ull m0 = lds64(&mr[moff]);
            ull m1 = lds64(&mr[CHUNK + moff]);
            accum(acc0, m0, x0, x1, x2, y0, y1, y2);
            accum(acc1, m1, x0, x1, x2, y0, y1, y2);
        }

        // keep the pipeline 3-deep (crosses pair boundaries)
        if (i + 3 < totseq) issue_seq(i + 3);

        // pair complete: butterfly-reduce 32 values, lane 0 commits
        if ((i & 3) == 3) {
            const int pr = warp + NWARP * (i >> 2);
            float v[32];
            #pragma unroll
            for (int k = 0; k < 16; k++) {
                float lo, hi;
                upk2(acc0[k], lo, hi); v[k] = lo + hi;
                upk2(acc1[k], lo, hi); v[16 + k] = lo + hi;
                acc0[k] = 0ULL; acc1[k] = 0ULL;
            }
            #pragma unroll
            for (int off = 16; off > 0; off >>= 1) {
                #pragma unroll
                for (int k = 0; k < 32; k++)
                    v[k] += __shfl_xor_sync(0xffffffffu, v[k], off);
            }
            if (lane == 0) {
                float* pp = &g_part[((size_t)b * SMN + gz * TPB + 2 * pr) * NCOMP];
                #pragma unroll
                for (int k = 0; k < 32; k++) atomicAdd(pp + k, v[k]);
            }
        }
    }

    // ---------------- last-block finalize (R8-validated pattern) ----------------
    __syncthreads();   // all warps in this block have issued their g_part atomics
    if (tid == 0) {
        __threadfence();                               // make our atomics visible
        unsigned int r = atomicAdd(&g_count, 1u);
        s_last = (r == TOTAL_BLOCKS - 1) ? 1u : 0u;
    }
    __syncthreads();
    if (!s_last) return;

    __threadfence();   // acquire-side ordering before reading g_part

    // reuse smem for the tiny epilogue accumulators
    float* csb = tile;          // [BB*SS] = 20
    float* ssb = tile + 32;
    if (tid < BB * SS) { csb[tid] = 0.0f; ssb[tid] = 0.0f; }
    __syncthreads();

    for (int idx = tid; idx < BB * SMN * CC; idx += THREADS) {
        int bb = idx / (SMN * CC);
        int r2 = idx % (SMN * CC);
        int s  = r2 / (MM * CC);
        int mc = r2 % (MM * CC);
        int m  = mc / CC;
        int c  = mc % CC;
        const float* p = &g_part[((size_t)bb * SMN + s * MM + m) * NCOMP];
        float inv  = __fdividef(1.0f, p[0] + EPSF);
        float mu1  = p[1 + c * 5 + 0] * inv;
        float mu2  = p[1 + c * 5 + 1] * inv;
        float mu11 = p[1 + c * 5 + 2] * inv;
        float mu22 = p[1 + c * 5 + 3] * inv;
        float mu12 = p[1 + c * 5 + 4] * inv;
        float s1  = mu11 - mu1 * mu1;
        float s2  = mu22 - mu2 * mu2;
        float s12 = mu12 - mu1 * mu2;
        float cs   = __fdividef(2.0f * s12 + K2C, s1 + s2 + K2C);
        float ssim = __fdividef(2.0f * mu1 * mu2 + K1C, mu1 * mu1 + mu2 * mu2 + K1C) * cs;
        cs   = fmaxf(cs, 0.0f);
        ssim = fmaxf(ssim, 0.0f);
        atomicAdd(&csb[bb * SS + s], cs);
        atomicAdd(&ssb[bb * SS + s], ssim);
    }
    __syncthreads();

    // re-zero partials + counter for the next invocation / graph replay
    for (int i = tid; i < BB * SMN * NCOMP; i += THREADS) g_part[i] = 0.0f;
    if (tid == 1) g_count = 0u;

    if (tid == 0) {
        const float invMC = 1.0f / (float)(MM * CC);
        float accb = 0.0f;
        #pragma unroll
        for (int bb = 0; bb < BB; bb++) {
            float prod = ssb[bb * SS + (SS - 1)] * invMC;
            #pragma unroll
            for (int s = 0; s < SS - 1; s++) prod *= csb[bb * SS + s] * invMC;
            accb += prod;
        }
        out[0] = accb / (float)BB;
    }
}

extern "C" void kernel_launch(void* const* d_in, const int* in_sizes, int n_in,
                              void* d_out, int out_size) {
    const float* X  = (const float*)d_in[0];
    const float* Y  = (const float*)d_in[1];
    const float* Mk = (const float*)d_in[2];
    float* out = (float*)d_out;

    cudaFuncSetAttribute(fused_kernel,
                         cudaFuncAttributeMaxDynamicSharedMemorySize, SMEM_TOTAL_B);
    dim3 grid(NTILES, BB, NGROUP);
    fused_kernel<<<grid, THREADS, SMEM_TOTAL_B>>>(X, Y, Mk, out);
}